// round 5
// baseline (speedup 1.0000x reference)
#include <cuda_runtime.h>

using u64 = unsigned long long;
#define FULL_MASK 0xFFFFFFFFu

constexpr int IN_DIM  = 256;
constexpr int D       = 32;
constexpr int RPT     = 8;            // rows per tile (= warps per block)
constexpr int NRF     = RPT * 3;      // 24 (row,feat) units per tile
constexpr int THREADS = 256;          // 8 warps
constexpr int PART_S  = 9;            // padded stride for warp partials (coprime 32)
constexpr float LN_EPS = 1e-5f;

struct Smem {
    float f[NRF * IN_DIM];            // 24576 B staged input rows
    float part[NRF * D * PART_S];     // 27648 B projection partials [rf][j][w]
    float x[NRF * D];                 // 3072 B  LN outputs
    float qkv[3][NRF * D];            // 9216 B
    float pooled[RPT][D];             // 1024 B
    float o1[RPT][D];                 // 1024 B
};                                    // ~65 KB -> 2 blocks/SM

__device__ __forceinline__ void ffma2(u64& d, u64 a, u64 b) {
    asm("fma.rn.f32x2 %0, %1, %2, %0;" : "+l"(d) : "l"(a), "l"(b));
}
__device__ __forceinline__ float hsum2(u64 a, u64 b) {
    return __uint_as_float((unsigned)a) + __uint_as_float((unsigned)(a >> 32))
         + __uint_as_float((unsigned)b) + __uint_as_float((unsigned)(b >> 32));
}
__device__ __forceinline__ float wsum(float v) {
    v += __shfl_xor_sync(FULL_MASK, v, 16);
    v += __shfl_xor_sync(FULL_MASK, v, 8);
    v += __shfl_xor_sync(FULL_MASK, v, 4);
    v += __shfl_xor_sync(FULL_MASK, v, 2);
    v += __shfl_xor_sync(FULL_MASK, v, 1);
    return v;
}

__global__ __launch_bounds__(THREADS, 2)
void msfe_kernel(const float* __restrict__ f1, const float* __restrict__ f4,
                 const float* __restrict__ fD,
                 const float* __restrict__ Wp,  const float* __restrict__ bp,
                 const float* __restrict__ ln_g, const float* __restrict__ ln_b,
                 const float* __restrict__ Wq,  const float* __restrict__ bq,
                 const float* __restrict__ Wk,  const float* __restrict__ bk,
                 const float* __restrict__ Wv,  const float* __restrict__ bv,
                 const float* __restrict__ Wo1, const float* __restrict__ bo1,
                 const float* __restrict__ Wo2, const float* __restrict__ bo2,
                 float* __restrict__ out, int B, int ntiles)
{
    extern __shared__ char smem_raw[];
    Smem* s = reinterpret_cast<Smem*>(smem_raw);

    const int tid  = threadIdx.x;
    const int lane = tid & 31;
    const int w    = tid >> 5;

    // ---- projection weights, ks-split: lane=(jh,ks) owns Wp[jh| jh+16][16k] ----
    const int jh = lane & 15;
    const int ks = lane >> 4;
    const int k0 = w * 32 + ks * 16;
    u64 wppA[8], wppB[8];
    {
        const u64* a = reinterpret_cast<const u64*>(Wp + jh * IN_DIM + k0);
        const u64* b = reinterpret_cast<const u64*>(Wp + (jh + 16) * IN_DIM + k0);
        #pragma unroll
        for (int c = 0; c < 8; c++) { wppA[c] = a[c]; wppB[c] = b[c]; }
    }

    // ---- small mats register-resident, role split by warp ----
    const float* Wsel = (w < 2) ? Wq : (w < 4) ? Wk : (w < 6) ? Wv : (w == 6) ? Wo1 : Wo2;
    const float* bsel = (w < 2) ? bq : (w < 4) ? bk : (w < 6) ? bv : (w == 6) ? bo1 : bo2;
    u64 wsm[16];
    {
        const u64* src = reinterpret_cast<const u64*>(Wsel + lane * D);
        #pragma unroll
        for (int c = 0; c < 16; c++) wsm[c] = src[c];
    }
    const float bsel_j = bsel[lane];

    const float bp_j  = bp [lane];
    const float g_j   = ln_g[lane];
    const float b_j   = ln_b[lane];
    const float bo2_j = bo2[lane];

    // ---- f-staging decomposition: 6 float4 per thread ----
    const float* bptr[6];
    int rloc[6];
    #pragma unroll
    for (int k2 = 0; k2 < 6; k2++) {
        int i  = tid + k2 * THREADS;
        int rf = i >> 6;
        int c  = i & 63;
        int r  = rf / 3;
        int ft = rf - 3 * r;
        rloc[k2] = r;
        const float* src = (ft == 0) ? f1 : (ft == 1) ? f4 : fD;
        bptr[k2] = src + (size_t)r * IN_DIM + c * 4;
    }

    float4 pf[6];
    {   // prologue: stage first tile
        int row0 = blockIdx.x * RPT;
        #pragma unroll
        for (int k2 = 0; k2 < 6; k2++) {
            int row = row0 + rloc[k2];
            pf[k2] = (row < B)
                ? *reinterpret_cast<const float4*>(bptr[k2] + (size_t)row0 * IN_DIM)
                : make_float4(0.f, 0.f, 0.f, 0.f);
        }
        float4* fdst = reinterpret_cast<float4*>(s->f);
        #pragma unroll
        for (int k2 = 0; k2 < 6; k2++) fdst[tid + k2 * THREADS] = pf[k2];
    }
    __syncthreads();

    for (int tile = blockIdx.x; tile < ntiles; tile += gridDim.x) {
        const int row0 = tile * RPT;
        const int nt   = tile + gridDim.x;
        const bool have_next = (nt < ntiles);

        // ---- P1: projection partials (ks-split, 2 j per thread) ----
        #pragma unroll 4
        for (int rf = 0; rf < NRF; rf++) {
            const ulonglong2* fp =
                reinterpret_cast<const ulonglong2*>(s->f + rf * IN_DIM + k0);
            u64 a0 = 0ull, a1 = 0ull, b0 = 0ull, b1 = 0ull;
            #pragma unroll
            for (int c = 0; c < 4; c++) {
                ulonglong2 fv = fp[c];           // 16-B broadcast (2 addrs/warp, 1 line)
                ffma2(a0, wppA[2 * c],     fv.x);
                ffma2(a1, wppA[2 * c + 1], fv.y);
                ffma2(b0, wppB[2 * c],     fv.x);
                ffma2(b1, wppB[2 * c + 1], fv.y);
            }
            float pA = hsum2(a0, a1);
            float pB = hsum2(b0, b1);
            pA += __shfl_xor_sync(FULL_MASK, pA, 16);   // combine ks halves
            pB += __shfl_xor_sync(FULL_MASK, pB, 16);
            s->part[(rf * D + lane) * PART_S + w] = (lane < 16) ? pA : pB;
        }
        __syncthreads();

        // ---- P2: prefetch next tile (LDG early) + reduce/relu/LN ----
        if (have_next) {
            int nrow0 = nt * RPT;
            #pragma unroll
            for (int k2 = 0; k2 < 6; k2++) {
                int row = nrow0 + rloc[k2];
                pf[k2] = (row < B)
                    ? *reinterpret_cast<const float4*>(bptr[k2] + (size_t)nrow0 * IN_DIM)
                    : make_float4(0.f, 0.f, 0.f, 0.f);
            }
        }
        #pragma unroll
        for (int idx = 0; idx < 3; idx++) {
            int rf = w + idx * 8;
            const float* pr = s->part + (rf * D + lane) * PART_S;
            float h = bp_j;
            #pragma unroll
            for (int ww = 0; ww < 8; ww++) h += pr[ww];
            h = fmaxf(h, 0.f);
            float mu  = wsum(h) * (1.f / 32.f);
            float dv  = h - mu;
            float var = wsum(dv * dv) * (1.f / 32.f);
            s->x[rf * D + lane] = g_j * dv * rsqrtf(var + LN_EPS) + b_j;
        }
        __syncthreads();

        // ---- P3: QKV (warps 0-5, reg weights, broadcast x) ----
        if (w < 6) {
            const int mat = w >> 1;
            const int rf0 = (w & 1) * (NRF / 2);
            #pragma unroll 3
            for (int rr = 0; rr < NRF / 2; rr++) {
                int rf = rf0 + rr;
                const ulonglong2* xp =
                    reinterpret_cast<const ulonglong2*>(s->x + rf * D);
                u64 a0 = 0ull, a1 = 0ull;
                #pragma unroll
                for (int c = 0; c < 8; c++) {
                    ulonglong2 xv = xp[c];
                    ffma2(a0, wsm[2 * c],     xv.x);
                    ffma2(a1, wsm[2 * c + 1], xv.y);
                }
                s->qkv[mat][rf * D + lane] = hsum2(a0, a1) + bsel_j;
            }
        }
        __syncthreads();

        // ---- P4: attention + softmax + pool (warp w = tile row w) ----
        {
            float qv[3], kv[3], vv[3];
            #pragma unroll
            for (int ss = 0; ss < 3; ss++) {
                int rf = w * 3 + ss;
                qv[ss] = s->qkv[0][rf * D + lane];
                kv[ss] = s->qkv[1][rf * D + lane];
                vv[ss] = s->qkv[2][rf * D + lane];
            }
            const float scale = 0.17677669529663687f;   // 1/sqrt(32)
            float att[3][3];
            #pragma unroll
            for (int ss = 0; ss < 3; ss++)
                #pragma unroll
                for (int tt = 0; tt < 3; tt++)
                    att[ss][tt] = wsum(qv[ss] * kv[tt]) * scale;

            float pooled = 0.f;
            #pragma unroll
            for (int ss = 0; ss < 3; ss++) {
                float m  = fmaxf(att[ss][0], fmaxf(att[ss][1], att[ss][2]));
                float e0 = __expf(att[ss][0] - m);
                float e1 = __expf(att[ss][1] - m);
                float e2 = __expf(att[ss][2] - m);
                float ri = 1.f / (e0 + e1 + e2);
                pooled += (e0 * vv[0] + e1 * vv[1] + e2 * vv[2]) * ri;
            }
            s->pooled[w][lane] = pooled * (1.f / 3.f);
        }
        __syncthreads();

        // ---- P5/P6: O1 (w6) -> named barrier -> O2 (w7); others store next f ----
        if (w == 6) {
            #pragma unroll
            for (int r = 0; r < RPT; r++) {
                const ulonglong2* pv = reinterpret_cast<const ulonglong2*>(s->pooled[r]);
                u64 a0 = 0ull, a1 = 0ull;
                #pragma unroll
                for (int c = 0; c < 8; c++) {
                    ulonglong2 xv = pv[c];
                    ffma2(a0, wsm[2 * c],     xv.x);
                    ffma2(a1, wsm[2 * c + 1], xv.y);
                }
                s->o1[r][lane] = fmaxf(hsum2(a0, a1) + bsel_j, 0.f);
            }
            asm volatile("bar.sync 1, 64;" ::: "memory");
            if (have_next) {   // w6 stores its f share while w7 runs O2
                float4* fdst = reinterpret_cast<float4*>(s->f);
                #pragma unroll
                for (int k2 = 0; k2 < 6; k2++) fdst[tid + k2 * THREADS] = pf[k2];
            }
        } else if (w == 7) {
            if (have_next) {
                float4* fdst = reinterpret_cast<float4*>(s->f);
                #pragma unroll
                for (int k2 = 0; k2 < 6; k2++) fdst[tid + k2 * THREADS] = pf[k2];
            }
            asm volatile("bar.sync 1, 64;" ::: "memory");
            #pragma unroll
            for (int r = 0; r < RPT; r++) {
                int row = row0 + r;
                if (row >= B) break;
                const ulonglong2* ov = reinterpret_cast<const ulonglong2*>(s->o1[r]);
                u64 a0 = 0ull, a1 = 0ull;
                #pragma unroll
                for (int c = 0; c < 8; c++) {
                    ulonglong2 xv = ov[c];
                    ffma2(a0, wsm[2 * c],     xv.x);
                    ffma2(a1, wsm[2 * c + 1], xv.y);
                }
                out[(size_t)row * D + lane] =
                    hsum2(a0, a1) + bo2_j + s->pooled[r][lane];
            }
        } else {
            if (have_next) {
                float4* fdst = reinterpret_cast<float4*>(s->f);
                #pragma unroll
                for (int k2 = 0; k2 < 6; k2++) fdst[tid + k2 * THREADS] = pf[k2];
            }
        }
        __syncthreads();   // f complete + o1/out done before next tile
    }
}

extern "C" void kernel_launch(void* const* d_in, const int* in_sizes, int n_in,
                              void* d_out, int out_size)
{
    const float* f1   = (const float*)d_in[0];
    const float* f4   = (const float*)d_in[1];
    const float* fD   = (const float*)d_in[2];
    const float* Wp   = (const float*)d_in[3];
    const float* bp   = (const float*)d_in[4];
    const float* ln_g = (const float*)d_in[5];
    const float* ln_b = (const float*)d_in[6];
    const float* Wq   = (const float*)d_in[7];
    const float* bq   = (const float*)d_in[8];
    const float* Wk   = (const float*)d_in[9];
    const float* bk   = (const float*)d_in[10];
    const float* Wv   = (const float*)d_in[11];
    const float* bv   = (const float*)d_in[12];
    const float* Wo1  = (const float*)d_in[13];
    const float* bo1  = (const float*)d_in[14];
    const float* Wo2  = (const float*)d_in[15];
    const float* bo2  = (const float*)d_in[16];

    const int B = in_sizes[0] / IN_DIM;
    const int ntiles = (B + RPT - 1) / RPT;
    const int smem_bytes = (int)sizeof(Smem);

    cudaFuncSetAttribute(msfe_kernel, cudaFuncAttributeMaxDynamicSharedMemorySize, smem_bytes);

    int grid = ntiles < 304 ? ntiles : 304;   // 2 blocks x 152 SMs, persistent
    msfe_kernel<<<grid, THREADS, smem_bytes>>>(
        f1, f4, fD, Wp, bp, ln_g, ln_b, Wq, bq, Wk, bk, Wv, bv,
        Wo1, bo1, Wo2, bo2, (float*)d_out, B, ntiles);
}